// round 5
// baseline (speedup 1.0000x reference)
#include <cuda_runtime.h>
#include <math.h>

// PatchReprogrammingEncoder: B=32,T=128 -> N=4096 rows; D=128, DP=768, H=4, HD=192, P=64, NTOK=15
#define NROWS   4096
#define D       128
#define DP      768
#define NTOK    15
#define NH      4
#define HD      192
#define NP      64
#define NTHREADS 576   // 18 warps; 3 t-groups x 192 j4-tiles in GEMM phases

typedef unsigned long long u64;

#define FMA2(d,a,b,c) asm("fma.rn.f32x2 %0, %1, %2, %3;" : "=l"(d) : "l"(a), "l"(b), "l"(c))
#define MUL2(d,a,b)   asm("mul.rn.f32x2 %0, %1, %2;"     : "=l"(d) : "l"(a), "l"(b))

__device__ __forceinline__ u64 pack2(float lo, float hi) {
    u64 r;
    asm("mov.b64 %0, {%1, %2};" : "=l"(r)
        : "r"(__float_as_uint(lo)), "r"(__float_as_uint(hi)));
    return r;
}
__device__ __forceinline__ float2 unpack2(u64 v) {
    unsigned lo, hi;
    asm("mov.b64 {%0, %1}, %2;" : "=r"(lo), "=r"(hi) : "l"(v));
    return make_float2(__uint_as_float(lo), __uint_as_float(hi));
}
__device__ __forceinline__ float f4_get(const float4& v, int i) {
    return (i == 0) ? v.x : (i == 1) ? v.y : (i == 2) ? v.z : v.w;
}

// K/V projections of protos are row-independent: computed once per launch.
// kT layout: [j=h*HD+d][p]  (p contiguous -> coalesced over p in score phase)
// v  layout: [p][j]          (j contiguous -> coalesced over j in rep phase)
__device__ float g_kT[DP * NP];
__device__ float g_v [NP * DP];

#define KV_PTILE 8
__global__ void kv_kernel(const float* __restrict__ protos,
                          const float* __restrict__ wk, const float* __restrict__ bk,
                          const float* __restrict__ wv, const float* __restrict__ bv) {
    int pblk = blockIdx.x;                       // 0..7 (8 protos each)
    int j = blockIdx.y * 192 + threadIdx.x;
    __shared__ __align__(16) float protoT[DP * KV_PTILE];   // [i][pp]
    for (int e = threadIdx.x; e < KV_PTILE * DP; e += 192) {
        int pp = e / DP, i = e % DP;
        protoT[i * KV_PTILE + pp] = protos[(pblk * KV_PTILE + pp) * DP + i];
    }
    __syncthreads();
    float bkj = bk[j], bvj = bv[j];
    float accK[KV_PTILE], accV[KV_PTILE];
#pragma unroll
    for (int pp = 0; pp < KV_PTILE; pp++) { accK[pp] = bkj; accV[pp] = bvj; }
#pragma unroll 4
    for (int i = 0; i < DP; i++) {
        float wkji = wk[i * DP + j];
        float wvji = wv[i * DP + j];
        float4 pr0 = *(const float4*)(protoT + i * KV_PTILE);
        float4 pr1 = *(const float4*)(protoT + i * KV_PTILE + 4);
#pragma unroll
        for (int pp = 0; pp < 4; pp++) {
            float p0 = f4_get(pr0, pp), p1 = f4_get(pr1, pp);
            accK[pp]     = fmaf(p0, wkji, accK[pp]);
            accK[pp + 4] = fmaf(p1, wkji, accK[pp + 4]);
            accV[pp]     = fmaf(p0, wvji, accV[pp]);
            accV[pp + 4] = fmaf(p1, wvji, accV[pp + 4]);
        }
    }
#pragma unroll
    for (int pp = 0; pp < KV_PTILE; pp++) {
        int p = pblk * KV_PTILE + pp;
        g_kT[j * NP + p] = accK[pp];
        g_v [p * DP + j] = accV[pp];
    }
}

// Fused per-row encoder: one CTA per row n.
// Dynamic smem (floats): pe[15*128] | q/rep[15*768] | attn[4*15*64] | srow[36+4pad] | red[3*5*6*2]
#define SM_PE   0
#define SM_Q    1920
#define SM_ATT  13440
#define SM_SROW 17280
#define SM_RED  17320
#define SM_FLOATS 17500
#define SMEM_BYTES (SM_FLOATS * 4)   // 70,000 B -> 1 CTA/SM, L1 carveout ~158 KB

__global__ void __launch_bounds__(NTHREADS, 1)
enc_kernel(const float* __restrict__ state,
           const float* __restrict__ w_scalar, const float* __restrict__ b_scalar,
           const float* __restrict__ w_patch,  const float* __restrict__ b_patch,
           const float* __restrict__ feat_emb,
           const float* __restrict__ pn_g, const float* __restrict__ pn_b,
           const float* __restrict__ wq,  const float* __restrict__ bq,
           const float* __restrict__ wp,  const float* __restrict__ bp,
           const float* __restrict__ wo,  const float* __restrict__ bo,
           const float* __restrict__ on_g, const float* __restrict__ on_b,
           float* __restrict__ outg) {
    extern __shared__ __align__(16) float sm[];
    float* pe   = sm + SM_PE;
    float* q    = sm + SM_Q;     // reused as rep after attention
    float* attn = sm + SM_ATT;   // scores, then softmax'd in place
    float* srow = sm + SM_SROW;
    float* red  = sm + SM_RED;   // LN partials: [tg][tt][warp] x {sum,sumsq}

    const int n    = blockIdx.x;
    const int tid  = threadIdx.x;
    const int lane = tid & 31;
    const int wid  = tid >> 5;

    if (tid < 36) srow[tid] = state[n * 36 + tid];
    __syncthreads();

    // ---- Phase 1: raw patch embedding pe (15 tokens x 128) ----
    for (int e = tid; e < NTOK * D; e += NTHREADS) {
        int t = e >> 7;
        int d = e & 127;
        float val;
        if (t == 0 || t == 1 || t == 14) {
            int f  = (t == 14) ? 2 : t;       // scalar-feature slot
            int fr = (t == 14) ? 5 : t;       // state row == feat_emb row
            float sc = srow[fr * 6 + 5];
            val = fmaf(sc, w_scalar[f * D + d], b_scalar[f * D + d]) + feat_emb[fr * D + d];
        } else {
            int tt = t - 2;
            int f  = tt >> 2;                 // 0..2  (state rows 2..4)
            int k  = tt & 3;                  // window start
            const float* sr = srow + (2 + f) * 6 + k;
            val = b_patch[f * D + d] + feat_emb[(2 + f) * D + d];
            val = fmaf(sr[0], w_patch[(f * 3 + 0) * D + d], val);
            val = fmaf(sr[1], w_patch[(f * 3 + 1) * D + d], val);
            val = fmaf(sr[2], w_patch[(f * 3 + 2) * D + d], val);
        }
        pe[e] = val;
    }
    __syncthreads();

    // ---- Phase 1b: LayerNorm(pe) over D=128, one warp per token ----
    if (wid < NTOK) {
        int t = wid;
        float x[4], s = 0.f, sq = 0.f;
#pragma unroll
        for (int c = 0; c < 4; c++) {
            x[c] = pe[t * D + lane + 32 * c];
            s += x[c]; sq += x[c] * x[c];
        }
#pragma unroll
        for (int o = 16; o; o >>= 1) {
            s  += __shfl_xor_sync(~0u, s,  o);
            sq += __shfl_xor_sync(~0u, sq, o);
        }
        float mean = s  * (1.f / 128.f);
        float var  = sq * (1.f / 128.f) - mean * mean;
        float rstd = rsqrtf(var + 1e-5f);
#pragma unroll
        for (int c = 0; c < 4; c++) {
            int d = lane + 32 * c;
            pe[t * D + d] = fmaf((x[c] - mean) * rstd, pn_g[d], pn_b[d]);
        }
    }
    __syncthreads();

    // ---- Phase 2: q = (pe @ wq + bq) * (1/sqrt(HD)), fold score scale into q ----
    // t-tile 5: 576 tasks, one per thread; wq line reused 5x in registers.
    {
        const float rs = rsqrtf((float)HD);
        const u64 scl2 = pack2(rs, rs);
        int tg = tid / 192;
        int j  = (tid - tg * 192) * 4;
        int t0 = tg * 5;
        float4 b4 = *(const float4*)(bq + j);
        u64 a01[5], a23[5];
#pragma unroll
        for (int tt = 0; tt < 5; tt++) {
            a01[tt] = pack2(b4.x, b4.y);
            a23[tt] = pack2(b4.z, b4.w);
        }
        const float* per = pe + t0 * D;
        const float* w   = wq + j;
        for (int i = 0; i < D; i += 4) {
            float4 p4[5];
#pragma unroll
            for (int tt = 0; tt < 5; tt++)
                p4[tt] = *(const float4*)(per + tt * D + i);
#pragma unroll
            for (int ii = 0; ii < 4; ii++) {
                ulonglong2 ww = *(const ulonglong2*)(w + (i + ii) * DP);
#pragma unroll
                for (int tt = 0; tt < 5; tt++) {
                    float pv = f4_get(p4[tt], ii);
                    u64 pp = pack2(pv, pv);
                    FMA2(a01[tt], pp, ww.x, a01[tt]);
                    FMA2(a23[tt], pp, ww.y, a23[tt]);
                }
            }
        }
#pragma unroll
        for (int tt = 0; tt < 5; tt++) {
            MUL2(a01[tt], a01[tt], scl2);
            MUL2(a23[tt], a23[tt], scl2);
            *(u64*)(q + (t0 + tt) * DP + j)     = a01[tt];
            *(u64*)(q + (t0 + tt) * DP + j + 2) = a23[tt];
        }
    }
    __syncthreads();

    // ---- Phase 3: scores[h,t,p] = q[t,h,:] . k[p,h,:] ----
    // t-tile 5: 192 tasks (h x tg x p4), p4 fastest -> coalesced 256B kT rows.
    if (tid < 192) {
        int p4  = tid & 15;
        int tg  = (tid >> 4) % 3;
        int h   = tid / 48;
        int p   = p4 * 4;
        int t0  = tg * 5;
        const float* qr = q + t0 * DP + h * HD;
        const float* kt = g_kT + (h * HD) * NP + p;
        u64 a01[5], a23[5];
#pragma unroll
        for (int tt = 0; tt < 5; tt++) { a01[tt] = 0ull; a23[tt] = 0ull; }
#pragma unroll 2
        for (int d = 0; d < HD; d += 4) {
            float4 q4[5];
#pragma unroll
            for (int tt = 0; tt < 5; tt++)
                q4[tt] = *(const float4*)(qr + tt * DP + d);
#pragma unroll
            for (int dd = 0; dd < 4; dd++) {
                ulonglong2 kk = *(const ulonglong2*)(kt + (d + dd) * NP);
#pragma unroll
                for (int tt = 0; tt < 5; tt++) {
                    float qv = f4_get(q4[tt], dd);
                    u64 qq = pack2(qv, qv);
                    FMA2(a01[tt], qq, kk.x, a01[tt]);
                    FMA2(a23[tt], qq, kk.y, a23[tt]);
                }
            }
        }
#pragma unroll
        for (int tt = 0; tt < 5; tt++) {
            float2 s01 = unpack2(a01[tt]), s23 = unpack2(a23[tt]);
            float* dst = attn + (h * NTOK + t0 + tt) * NP + p;
            *(float4*)dst = make_float4(s01.x, s01.y, s23.x, s23.y);
        }
    }
    __syncthreads();

    // ---- Phase 3b: softmax over p (64), one warp per (h,t) row ----
    for (int r = wid; r < NH * NTOK; r += NTHREADS / 32) {
        float x0 = attn[r * NP + lane];
        float x1 = attn[r * NP + lane + 32];
        float m = fmaxf(x0, x1);
#pragma unroll
        for (int o = 16; o; o >>= 1) m = fmaxf(m, __shfl_xor_sync(~0u, m, o));
        float e0 = __expf(x0 - m);
        float e1 = __expf(x1 - m);
        float s = e0 + e1;
#pragma unroll
        for (int o = 16; o; o >>= 1) s += __shfl_xor_sync(~0u, s, o);
        float inv = 1.f / s;
        attn[r * NP + lane]      = e0 * inv;
        attn[r * NP + lane + 32] = e1 * inv;
    }
    __syncthreads();

    // ---- Phase 4: rep[t,j] = sum_p attn[h(j),t,p] * v[p,j]  (overwrites q) ----
    {
        int tg = tid / 192;
        int j  = (tid - tg * 192) * 4;
        int t0 = tg * 5;
        int h  = j / HD;                      // j4 tile never straddles a head
        const float* ar = attn + (h * NTOK + t0) * NP;
        const float* vv = g_v + j;
        u64 a01[5], a23[5];
#pragma unroll
        for (int tt = 0; tt < 5; tt++) { a01[tt] = 0ull; a23[tt] = 0ull; }
        for (int p = 0; p < NP; p += 4) {
            float4 a4[5];
#pragma unroll
            for (int tt = 0; tt < 5; tt++)
                a4[tt] = *(const float4*)(ar + tt * NP + p);
#pragma unroll
            for (int pp2 = 0; pp2 < 4; pp2++) {
                ulonglong2 vw = *(const ulonglong2*)(vv + (p + pp2) * DP);
#pragma unroll
                for (int tt = 0; tt < 5; tt++) {
                    float av = f4_get(a4[tt], pp2);
                    u64 aa = pack2(av, av);
                    FMA2(a01[tt], aa, vw.x, a01[tt]);
                    FMA2(a23[tt], aa, vw.y, a23[tt]);
                }
            }
        }
#pragma unroll
        for (int tt = 0; tt < 5; tt++) {
            *(u64*)(q + (t0 + tt) * DP + j)     = a01[tt];
            *(u64*)(q + (t0 + tt) * DP + j + 2) = a23[tt];
        }
    }
    __syncthreads();

    // ---- Phase 5+6 fused: out = rep @ wo + bo + pe @ wp + bp, then LN in registers ----
    // 576 tasks = 3 t-groups x 192 j4-tiles. LN stats via warp shuffle + 6-warp smem
    // partials per (tg,token); normalized values written straight to global (STG.128).
    {
        int tg   = tid / 192;
        int j    = (tid - tg * 192) * 4;
        int t0   = tg * 5;
        int wsub = (tid - tg * 192) >> 5;     // warp index within t-group, 0..5
        float4 bo4 = *(const float4*)(bo + j);
        float4 bp4 = *(const float4*)(bp + j);
        u64 a01[5], a23[5];
#pragma unroll
        for (int tt = 0; tt < 5; tt++) {
            a01[tt] = pack2(bo4.x + bp4.x, bo4.y + bp4.y);
            a23[tt] = pack2(bo4.z + bp4.z, bo4.w + bp4.w);
        }
        const float* rr = q + t0 * DP;        // rep rows t0..t0+4
        const float* w  = wo + j;
        for (int i = 0; i < DP; i += 4) {
            float4 r4[5];
#pragma unroll
            for (int tt = 0; tt < 5; tt++)
                r4[tt] = *(const float4*)(rr + tt * DP + i);
#pragma unroll
            for (int ii = 0; ii < 4; ii++) {
                ulonglong2 ww = *(const ulonglong2*)(w + (i + ii) * DP);
#pragma unroll
                for (int tt = 0; tt < 5; tt++) {
                    float rv = f4_get(r4[tt], ii);
                    u64 rp = pack2(rv, rv);
                    FMA2(a01[tt], rp, ww.x, a01[tt]);
                    FMA2(a23[tt], rp, ww.y, a23[tt]);
                }
            }
        }
        const float* per = pe + t0 * D;
        const float* w2  = wp + j;
        for (int i = 0; i < D; i += 4) {
            float4 p4[5];
#pragma unroll
            for (int tt = 0; tt < 5; tt++)
                p4[tt] = *(const float4*)(per + tt * D + i);
#pragma unroll
            for (int ii = 0; ii < 4; ii++) {
                ulonglong2 ww = *(const ulonglong2*)(w2 + (i + ii) * DP);
#pragma unroll
                for (int tt = 0; tt < 5; tt++) {
                    float pv = f4_get(p4[tt], ii);
                    u64 pp = pack2(pv, pv);
                    FMA2(a01[tt], pp, ww.x, a01[tt]);
                    FMA2(a23[tt], pp, ww.y, a23[tt]);
                }
            }
        }
        // LN partial sums: warp reduce, then per-warp partials to smem.
        float2 o01[5], o23[5];
#pragma unroll
        for (int tt = 0; tt < 5; tt++) {
            o01[tt] = unpack2(a01[tt]);
            o23[tt] = unpack2(a23[tt]);
            float s  = o01[tt].x + o01[tt].y + o23[tt].x + o23[tt].y;
            float sq = o01[tt].x * o01[tt].x + o01[tt].y * o01[tt].y
                     + o23[tt].x * o23[tt].x + o23[tt].y * o23[tt].y;
#pragma unroll
            for (int o = 16; o; o >>= 1) {
                s  += __shfl_xor_sync(~0u, s,  o);
                sq += __shfl_xor_sync(~0u, sq, o);
            }
            if (lane == 0) {
                float2* rp = (float2*)red + (tg * 5 + tt) * 6 + wsub;
                *rp = make_float2(s, sq);
            }
        }
        __syncthreads();
        float4 g4 = *(const float4*)(on_g + j);
        float4 b4n = *(const float4*)(on_b + j);
#pragma unroll
        for (int tt = 0; tt < 5; tt++) {
            const float2* rp = (const float2*)red + (tg * 5 + tt) * 6;
            float s = 0.f, sq = 0.f;
#pragma unroll
            for (int ww2 = 0; ww2 < 6; ww2++) {
                float2 pr = rp[ww2];
                s += pr.x; sq += pr.y;
            }
            float mean = s  * (1.f / 768.f);
            float var  = sq * (1.f / 768.f) - mean * mean;
            float rstd = rsqrtf(var + 1e-5f);
            float4 res;
            res.x = fmaf((o01[tt].x - mean) * rstd, g4.x, b4n.x);
            res.y = fmaf((o01[tt].y - mean) * rstd, g4.y, b4n.y);
            res.z = fmaf((o23[tt].x - mean) * rstd, g4.z, b4n.z);
            res.w = fmaf((o23[tt].y - mean) * rstd, g4.w, b4n.w);
            *(float4*)(outg + ((size_t)n * NTOK + t0 + tt) * DP + j) = res;
        }
    }
}

extern "C" void kernel_launch(void* const* d_in, const int* in_sizes, int n_in,
                              void* d_out, int out_size) {
    const float* state    = (const float*)d_in[0];
    const float* w_scalar = (const float*)d_in[1];
    const float* b_scalar = (const float*)d_in[2];
    const float* w_patch  = (const float*)d_in[3];
    const float* b_patch  = (const float*)d_in[4];
    const float* feat_emb = (const float*)d_in[5];
    const float* pn_g     = (const float*)d_in[6];
    const float* pn_b     = (const float*)d_in[7];
    const float* wq       = (const float*)d_in[8];
    const float* bq       = (const float*)d_in[9];
    const float* wk       = (const float*)d_in[10];
    const float* bk       = (const float*)d_in[11];
    const float* wv       = (const float*)d_in[12];
    const float* bv       = (const float*)d_in[13];
    const float* wp       = (const float*)d_in[14];
    const float* bp       = (const float*)d_in[15];
    const float* wo       = (const float*)d_in[16];
    const float* bo       = (const float*)d_in[17];
    const float* on_g     = (const float*)d_in[18];
    const float* on_b     = (const float*)d_in[19];
    const float* protos   = (const float*)d_in[20];
    float* out = (float*)d_out;

    cudaFuncSetAttribute(enc_kernel, cudaFuncAttributeMaxDynamicSharedMemorySize, SMEM_BYTES);

    kv_kernel<<<dim3(NP / KV_PTILE, 4), 192>>>(protos, wk, bk, wv, bv);
    enc_kernel<<<NROWS, NTHREADS, SMEM_BYTES>>>(
        state, w_scalar, b_scalar, w_patch, b_patch, feat_emb,
        pn_g, pn_b, wq, bq, wp, bp, wo, bo, on_g, on_b, out);
}